// round 9
// baseline (speedup 1.0000x reference)
#include <cuda_runtime.h>
#include <cuda_bf16.h>
#include <math.h>

// Problem constants (fixed by the dataset)
#define N_    8192
#define C_    19
#define M_    10
#define CM_   190         // C_*M_
#define K_    64
#define PVN   (C_*M_*K_)  // 12160
#define K2    128         // GEMM K = 2*K_  ( [r|a] x [p^2|p] )
#define MB    32          // n-rows per block
#define SA    132         // A smem row stride in bf16 elems

__device__ int d_flag;                          // proto_var uniform?
// B in mma fragment layout: index = (tile*8 + ks)*32 + lane, value = {b0,b1}
__device__ __align__(16) uint2 g_fragB[24 * 8 * 32];

// ---- mma.sync m16n8k16 bf16 -> f32 ------------------------------------------
__device__ __forceinline__ void mma16816(float* d,
                                         unsigned a0, unsigned a1,
                                         unsigned a2, unsigned a3,
                                         unsigned b0, unsigned b1) {
    asm volatile(
        "mma.sync.aligned.m16n8k16.row.col.f32.bf16.bf16.f32 "
        "{%0,%1,%2,%3}, {%4,%5,%6,%7}, {%8,%9}, {%0,%1,%2,%3};"
        : "+f"(d[0]), "+f"(d[1]), "+f"(d[2]), "+f"(d[3])
        : "r"(a0), "r"(a1), "r"(a2), "r"(a3), "r"(b0), "r"(b1));
}

// BT[cm][k] = p[cm][k]^2 (k<64) ; p[cm][k-64] (k>=64) ; 0 for cm>=190
__device__ __forceinline__ float bt_elem(const float* p, int cm, int k) {
    if (cm >= CM_) return 0.0f;
    const float pe = p[cm * K_ + (k & (K_ - 1))];
    return (k < K_) ? pe * pe : pe;
}

// ---- kernel 1: uniformity check (block 0) + build fragB (blocks 1..24) ------
__global__ void prep_kernel(const float* __restrict__ p,
                            const float* __restrict__ pv) {
    // Let the dependent main kernel begin launching immediately; it grid-syncs
    // before consuming d_flag / g_fragB.
    cudaTriggerProgrammaticLaunchCompletion();

    const int t = threadIdx.x;
    if (blockIdx.x == 0) {
        const float v0 = pv[0];
        int ok = 1;
        #pragma unroll 4
        for (int i = t; i < PVN; i += 256) ok &= (pv[i] == v0);
        const int all = __syncthreads_and(ok);
        if (t == 0) d_flag = all;
        return;
    }
    // 24 blocks x 8 warps = 192 tasks = 24 tiles x 8 ksteps
    const int task = (blockIdx.x - 1) * 8 + (t >> 5);   // tile*8 + ks
    const int lane = t & 31;
    const int g    = lane >> 2;
    const int tg   = lane & 3;
    const int nrow = (task >> 3) * 8 + g;
    const int k0   = (task & 7) * 16 + 2 * tg;

    const __nv_bfloat162 b0 = __floats2bfloat162_rn(
        bt_elem(p, nrow, k0),     bt_elem(p, nrow, k0 + 1));
    const __nv_bfloat162 b1 = __floats2bfloat162_rn(
        bt_elem(p, nrow, k0 + 8), bt_elem(p, nrow, k0 + 9));
    uint2 v;
    v.x = *reinterpret_cast<const unsigned*>(&b0);
    v.y = *reinterpret_cast<const unsigned*>(&b1);
    g_fragB[task * 32 + lane] = v;
}

// ---- kernel 2: precompute + tensor-core GEMM + coalesced epilogue -----------
__global__ void __launch_bounds__(256, 4)
main_kernel(const float* __restrict__ x,  const float* __restrict__ xv,
            const float* __restrict__ p,  const float* __restrict__ pv,
            float* __restrict__ out) {
    __shared__ __align__(16) __nv_bfloat16 As[MB * SA]; // [row][ r(64)|a(64) ]
    __shared__ float base_s[MB];
    __shared__ __align__(16) float out_s[MB * CM_];     // 24320 B staging

    const int t  = threadIdx.x;
    const int n0 = blockIdx.x * MB;

    // ===== phase 1 (independent of prep): x/xv loads + precompute ===========
    const int row = t >> 3;              // 0..31
    const int kq  = t & 7;               // 8-k chunk
    const float* xrow = x  + (n0 + row) * K_ + kq * 8;
    const float* vrow = xv + (n0 + row) * K_ + kq * 8;
    const float4 x0 = __ldg(reinterpret_cast<const float4*>(xrow));
    const float4 x1 = __ldg(reinterpret_cast<const float4*>(xrow + 4));
    const float4 v0v = __ldg(reinterpret_cast<const float4*>(vrow));
    const float4 v1v = __ldg(reinterpret_cast<const float4*>(vrow + 4));
    const float v0 = __ldg(pv);

    const float xs[8] = {x0.x, x0.y, x0.z, x0.w, x1.x, x1.y, x1.z, x1.w};
    const float vs[8] = {v0v.x, v0v.y, v0v.z, v0v.w, v1v.x, v1v.y, v1v.z, v1v.w};
    float rr[8], aa[8], prod = 1.0f, sxr = 0.0f;
    #pragma unroll
    for (int e = 0; e < 8; ++e) {
        const float s = vs[e] + v0;
        const float r = __fdividef(1.0f, s);
        prod *= s;
        sxr   = fmaf(xs[e] * xs[e], r, sxr);
        rr[e] = r;
        aa[e] = -2.0f * xs[e] * r;
    }
    __nv_bfloat16* arow = As + row * SA + kq * 8;
    #pragma unroll
    for (int q = 0; q < 4; ++q) {
        reinterpret_cast<__nv_bfloat162*>(arow)[q] =
            __floats2bfloat162_rn(rr[2*q], rr[2*q+1]);
        reinterpret_cast<__nv_bfloat162*>(arow + K_)[q] =
            __floats2bfloat162_rn(aa[2*q], aa[2*q+1]);
    }
    float tv = sxr + __logf(prod);   // s in (v0, v0+1): no overflow
    tv += __shfl_xor_sync(0xffffffffu, tv, 1);
    tv += __shfl_xor_sync(0xffffffffu, tv, 2);
    tv += __shfl_xor_sync(0xffffffffu, tv, 4);
    if (kq == 0) base_s[row] = tv;
    __syncthreads();

    // ===== wait for prep results (flag + fragB) ==============================
    cudaGridDependencySynchronize();

    if (d_flag) {
        // ===== GEMM: 2 m16 tiles; 8 warps x 3 n8-tiles; b reused across m ===
        const int w    = t >> 5;
        const int lane = t & 31;
        const int g    = lane >> 2;
        const int tg   = lane & 3;

        float acc[2][3][4];
        #pragma unroll
        for (int mt = 0; mt < 2; ++mt)
            #pragma unroll
            for (int j = 0; j < 3; ++j)
                #pragma unroll
                for (int q = 0; q < 4; ++q) acc[mt][j][q] = 0.0f;

        #pragma unroll
        for (int j = 0; j < 3; ++j) {
            // batch-load all 8 ksteps of this n-tile (independent LDG.64s)
            uint2 b8[8];
            const uint2* fB = g_fragB + ((w * 3 + j) * 8) * 32 + lane;
            #pragma unroll
            for (int ks = 0; ks < 8; ++ks) b8[ks] = __ldg(fB + ks * 32);

            #pragma unroll
            for (int mt = 0; mt < 2; ++mt) {
                const __nv_bfloat16* ar0 = As + (mt * 16 + g) * SA;
                const __nv_bfloat16* ar1 = ar0 + 8 * SA;
                #pragma unroll
                for (int ks = 0; ks < 8; ++ks) {
                    const int k0 = ks * 16 + 2 * tg;
                    const unsigned a0 = *reinterpret_cast<const unsigned*>(ar0 + k0);
                    const unsigned a1 = *reinterpret_cast<const unsigned*>(ar1 + k0);
                    const unsigned a2 = *reinterpret_cast<const unsigned*>(ar0 + k0 + 8);
                    const unsigned a3 = *reinterpret_cast<const unsigned*>(ar1 + k0 + 8);
                    mma16816(acc[mt][j], a0, a1, a2, a3, b8[ks].x, b8[ks].y);
                }
            }
        }

        // ===== epilogue: stage in smem, then contiguous float4 stores ========
        #pragma unroll
        for (int mt = 0; mt < 2; ++mt) {
            const int r0  = mt * 16 + g;
            const float bs0 = base_s[r0];
            const float bs1 = base_s[r0 + 8];
            #pragma unroll
            for (int j = 0; j < 3; ++j) {
                const int cm = (w * 3 + j) * 8 + 2 * tg;
                if (cm < CM_) {
                    float2 o0, o1;
                    o0.x = -0.0078125f * (acc[mt][j][0] + bs0);
                    o0.y = -0.0078125f * (acc[mt][j][1] + bs0);
                    o1.x = -0.0078125f * (acc[mt][j][2] + bs1);
                    o1.y = -0.0078125f * (acc[mt][j][3] + bs1);
                    *reinterpret_cast<float2*>(out_s +  r0      * CM_ + cm) = o0;
                    *reinterpret_cast<float2*>(out_s + (r0 + 8) * CM_ + cm) = o1;
                }
            }
        }
        __syncthreads();

        // block output = contiguous span out[n0*190 .. n0*190 + 6080)
        const float4* src = reinterpret_cast<const float4*>(out_s);
        float4* dst = reinterpret_cast<float4*>(out + n0 * CM_);
        #pragma unroll
        for (int i = 0; i < 6; ++i) {
            const int idx = t + i * 256;
            if (idx < (MB * CM_) / 4) dst[idx] = src[idx];
        }
    } else {
        // ================= GENERAL FALLBACK (non-uniform pv) =================
        for (int idx = t; idx < MB * CM_; idx += 256) {
            const int j  = idx / CM_;
            const int cm = idx % CM_;
            const int n  = n0 + j;
            float acc = 0.0f;
            for (int k = 0; k < K_; ++k) {
                const float s = xv[n * K_ + k] + pv[cm * K_ + k];
                const float d = p[cm * K_ + k] - x[n * K_ + k];
                acc += d * d / s + logf(s);
            }
            out[n * CM_ + cm] = -0.5f * acc * (1.0f / (float)K_);
        }
    }
}

// ---- launch -----------------------------------------------------------------
extern "C" void kernel_launch(void* const* d_in, const int* in_sizes, int n_in,
                              void* d_out, int out_size) {
    const float* x  = (const float*)d_in[0];   // [8192,64]
    const float* xv = (const float*)d_in[1];   // [8192,64]
    const float* p  = (const float*)d_in[2];   // [19,10,64]
    const float* pv = (const float*)d_in[3];   // [19,10,64]
    float* out = (float*)d_out;                // [8192,19,10]

    prep_kernel<<<25, 256>>>(p, pv);

    // main kernel with programmatic dependent launch: overlaps its
    // prep-independent phase (x/xv loads + precompute) with prep_kernel.
    cudaLaunchConfig_t cfg = {};
    cfg.gridDim  = dim3(N_ / MB);
    cfg.blockDim = dim3(256);
    cfg.dynamicSmemBytes = 0;
    cfg.stream = 0;
    cudaLaunchAttribute attr[1];
    attr[0].id = cudaLaunchAttributeProgrammaticStreamSerialization;
    attr[0].val.programmaticStreamSerializationAllowed = 1;
    cfg.attrs = attr;
    cfg.numAttrs = 1;
    cudaLaunchKernelEx(&cfg, main_kernel, x, xv, p, pv, out);
}

// round 10
// speedup vs baseline: 1.2209x; 1.2209x over previous
#include <cuda_runtime.h>
#include <cuda_bf16.h>
#include <math.h>

// Problem constants (fixed by the dataset)
#define N_    8192
#define C_    19
#define M_    10
#define CM_   190         // C_*M_
#define K_    64
#define PVN   (C_*M_*K_)  // 12160
#define MB    16          // n-rows per block
#define SA    132         // A smem row stride in bf16 elems
#define NPREP 25          // prep blocks

__device__ int d_ok[NPREP];                     // per-prep-block uniformity
// B in mma fragment layout: index = (tile*8 + ks)*32 + lane, value = {b0,b1}
__device__ __align__(16) uint2 g_fragB[24 * 8 * 32];

// ---- mma.sync m16n8k16 bf16 -> f32 ------------------------------------------
__device__ __forceinline__ void mma16816(float* d,
                                         unsigned a0, unsigned a1,
                                         unsigned a2, unsigned a3,
                                         unsigned b0, unsigned b1) {
    asm volatile(
        "mma.sync.aligned.m16n8k16.row.col.f32.bf16.bf16.f32 "
        "{%0,%1,%2,%3}, {%4,%5,%6,%7}, {%8,%9}, {%0,%1,%2,%3};"
        : "+f"(d[0]), "+f"(d[1]), "+f"(d[2]), "+f"(d[3])
        : "r"(a0), "r"(a1), "r"(a2), "r"(a3), "r"(b0), "r"(b1));
}

// BT[cm][k] = p[cm][k]^2 (k<64) ; p[cm][k-64] (k>=64) ; 0 for cm>=190
__device__ __forceinline__ float bt_elem(const float* p, int cm, int k) {
    if (cm >= CM_) return 0.0f;
    const float pe = p[cm * K_ + (k & (K_ - 1))];
    return (k < K_) ? pe * pe : pe;
}

// ---- kernel 1: sliced uniformity check + build fragB -------------------------
__global__ void prep_kernel(const float* __restrict__ p,
                            const float* __restrict__ pv) {
    cudaTriggerProgrammaticLaunchCompletion();

    const int t = threadIdx.x;
    const int b = blockIdx.x;

    // --- uniformity check, slice per block: 2 elements per thread ----------
    const float v0 = pv[0];
    int ok = 1;
    #pragma unroll
    for (int i = 0; i < 2; ++i) {
        const int idx = (b * 256 + t) * 2 + i;   // covers 12800 >= PVN
        if (idx < PVN) ok &= (pv[idx] == v0);
    }
    const int all = __syncthreads_and(ok);
    if (t == 0) d_ok[b] = all;

    if (b == 0) return;
    // --- fragB build: blocks 1..24, 8 warps = 8 ksteps of one tile ----------
    const int task = (b - 1) * 8 + (t >> 5);     // tile*8 + ks
    const int lane = t & 31;
    const int g    = lane >> 2;
    const int tg   = lane & 3;
    const int nrow = (task >> 3) * 8 + g;
    const int k0   = (task & 7) * 16 + 2 * tg;

    const __nv_bfloat162 b0 = __floats2bfloat162_rn(
        bt_elem(p, nrow, k0),     bt_elem(p, nrow, k0 + 1));
    const __nv_bfloat162 b1 = __floats2bfloat162_rn(
        bt_elem(p, nrow, k0 + 8), bt_elem(p, nrow, k0 + 9));
    uint2 v;
    v.x = *reinterpret_cast<const unsigned*>(&b0);
    v.y = *reinterpret_cast<const unsigned*>(&b1);
    g_fragB[task * 32 + lane] = v;
}

// ---- kernel 2: precompute + tensor-core GEMM + coalesced epilogue -----------
__global__ void __launch_bounds__(256, 5)
main_kernel(const float* __restrict__ x,  const float* __restrict__ xv,
            const float* __restrict__ p,  const float* __restrict__ pv,
            float* __restrict__ out) {
    __shared__ __align__(16) __nv_bfloat16 As[MB * SA]; // [row][ r(64)|a(64) ]
    __shared__ float base_s[MB];
    __shared__ __align__(16) float out_s[MB * CM_];     // 12160 B staging

    const int t  = threadIdx.x;
    const int n0 = blockIdx.x * MB;
    const int lane = t & 31;

    // ===== phase 1 (independent of prep): x/xv loads + precompute ===========
    const int row = t >> 4;              // 0..15
    const int kq  = t & 15;              // 4-k chunk
    const float4 xx = __ldg(reinterpret_cast<const float4*>(
                          x  + (n0 + row) * K_ + kq * 4));
    const float4 vv = __ldg(reinterpret_cast<const float4*>(
                          xv + (n0 + row) * K_ + kq * 4));
    const float v0 = __ldg(pv);

    const float xs[4] = {xx.x, xx.y, xx.z, xx.w};
    const float vs[4] = {vv.x, vv.y, vv.z, vv.w};
    float rr[4], aa[4], prod = 1.0f, sxr = 0.0f;
    #pragma unroll
    for (int e = 0; e < 4; ++e) {
        const float s = vs[e] + v0;
        const float r = __fdividef(1.0f, s);
        prod *= s;
        sxr   = fmaf(xs[e] * xs[e], r, sxr);
        rr[e] = r;
        aa[e] = -2.0f * xs[e] * r;
    }
    __nv_bfloat16* arow = As + row * SA + kq * 4;
    reinterpret_cast<__nv_bfloat162*>(arow)[0]      = __floats2bfloat162_rn(rr[0], rr[1]);
    reinterpret_cast<__nv_bfloat162*>(arow)[1]      = __floats2bfloat162_rn(rr[2], rr[3]);
    reinterpret_cast<__nv_bfloat162*>(arow + K_)[0] = __floats2bfloat162_rn(aa[0], aa[1]);
    reinterpret_cast<__nv_bfloat162*>(arow + K_)[1] = __floats2bfloat162_rn(aa[2], aa[3]);

    float tv = sxr + __logf(prod);   // s in (v0, v0+1): no overflow
    tv += __shfl_xor_sync(0xffffffffu, tv, 1);
    tv += __shfl_xor_sync(0xffffffffu, tv, 2);
    tv += __shfl_xor_sync(0xffffffffu, tv, 4);
    tv += __shfl_xor_sync(0xffffffffu, tv, 8);
    if (kq == 0) base_s[row] = tv;
    __syncthreads();

    // ===== wait for prep results, then AND the 25 slice-flags per warp ======
    cudaGridDependencySynchronize();
    const int my_ok = (lane < NPREP) ? d_ok[lane] : 1;
    const int flag  = __all_sync(0xffffffffu, my_ok != 0);

    if (flag) {
        // ===== GEMM: one m16 tile; 8 warps x 3 n8-tiles ======================
        const int w  = t >> 5;
        const int g  = lane >> 2;
        const int tg = lane & 3;

        const __nv_bfloat16* ar0 = As + g * SA;
        const __nv_bfloat16* ar1 = ar0 + 8 * SA;

        float acc[3][4];
        #pragma unroll
        for (int j = 0; j < 3; ++j)
            #pragma unroll
            for (int q = 0; q < 4; ++q) acc[j][q] = 0.0f;

        #pragma unroll
        for (int j = 0; j < 3; ++j) {
            // batch-load all 8 ksteps of this n-tile (independent LDG.64s)
            uint2 b8[8];
            const uint2* fB = g_fragB + ((w * 3 + j) * 8) * 32 + lane;
            #pragma unroll
            for (int ks = 0; ks < 8; ++ks) b8[ks] = __ldg(fB + ks * 32);

            #pragma unroll
            for (int ks = 0; ks < 8; ++ks) {
                const int k0 = ks * 16 + 2 * tg;
                const unsigned a0 = *reinterpret_cast<const unsigned*>(ar0 + k0);
                const unsigned a1 = *reinterpret_cast<const unsigned*>(ar1 + k0);
                const unsigned a2 = *reinterpret_cast<const unsigned*>(ar0 + k0 + 8);
                const unsigned a3 = *reinterpret_cast<const unsigned*>(ar1 + k0 + 8);
                mma16816(acc[j], a0, a1, a2, a3, b8[ks].x, b8[ks].y);
            }
        }

        // ===== epilogue: stage in smem, then contiguous float4 stores ========
        const float bs0 = base_s[g];
        const float bs1 = base_s[g + 8];
        #pragma unroll
        for (int j = 0; j < 3; ++j) {
            const int cm = (w * 3 + j) * 8 + 2 * tg;
            if (cm < CM_) {
                float2 o0, o1;
                o0.x = -0.0078125f * (acc[j][0] + bs0);
                o0.y = -0.0078125f * (acc[j][1] + bs0);
                o1.x = -0.0078125f * (acc[j][2] + bs1);
                o1.y = -0.0078125f * (acc[j][3] + bs1);
                *reinterpret_cast<float2*>(out_s +  g      * CM_ + cm) = o0;
                *reinterpret_cast<float2*>(out_s + (g + 8) * CM_ + cm) = o1;
            }
        }
        __syncthreads();

        // block output = contiguous span out[n0*190 .. n0*190 + 3040)
        const float4* src = reinterpret_cast<const float4*>(out_s);
        float4* dst = reinterpret_cast<float4*>(out + n0 * CM_);
        #pragma unroll
        for (int i = 0; i < 3; ++i) {
            const int idx = t + i * 256;
            if (idx < (MB * CM_) / 4) dst[idx] = src[idx];
        }
    } else {
        // ================= GENERAL FALLBACK (non-uniform pv) =================
        for (int idx = t; idx < MB * CM_; idx += 256) {
            const int j  = idx / CM_;
            const int cm = idx % CM_;
            const int n  = n0 + j;
            float acc = 0.0f;
            for (int k = 0; k < K_; ++k) {
                const float s = xv[n * K_ + k] + pv[cm * K_ + k];
                const float d = p[cm * K_ + k] - x[n * K_ + k];
                acc += d * d / s + logf(s);
            }
            out[n * CM_ + cm] = -0.5f * acc * (1.0f / (float)K_);
        }
    }
}

// ---- launch -----------------------------------------------------------------
extern "C" void kernel_launch(void* const* d_in, const int* in_sizes, int n_in,
                              void* d_out, int out_size) {
    const float* x  = (const float*)d_in[0];   // [8192,64]
    const float* xv = (const float*)d_in[1];   // [8192,64]
    const float* p  = (const float*)d_in[2];   // [19,10,64]
    const float* pv = (const float*)d_in[3];   // [19,10,64]
    float* out = (float*)d_out;                // [8192,19,10]

    prep_kernel<<<NPREP, 256>>>(p, pv);

    // main kernel with programmatic dependent launch: overlaps its
    // prep-independent phase (x/xv loads + precompute) with prep_kernel.
    cudaLaunchConfig_t cfg = {};
    cfg.gridDim  = dim3(N_ / MB);
    cfg.blockDim = dim3(256);
    cfg.dynamicSmemBytes = 0;
    cfg.stream = 0;
    cudaLaunchAttribute attr[1];
    attr[0].id = cudaLaunchAttributeProgrammaticStreamSerialization;
    attr[0].val.programmaticStreamSerializationAllowed = 1;
    cfg.attrs = attr;
    cfg.numAttrs = 1;
    cudaLaunchKernelEx(&cfg, main_kernel, x, xv, p, pv, out);
}